// round 1
// baseline (speedup 1.0000x reference)
#include <cuda_runtime.h>
#include <math.h>

#define SEQ  8192
#define DIN  512
#define D    64
#define BM   64
#define BN   64
#define STR  68   // padded row stride (floats), 16B-aligned rows

// Scratch for Q, K, V (no cudaMalloc allowed)
__device__ float g_QKV[3][SEQ * D];

// ---------------------------------------------------------------------------
// Kernel 1: QKV projection.  out = x @ W   ([SEQ,DIN] @ [DIN,D] -> [SEQ,D])
// grid (SEQ/64, 3), 256 threads.  blockIdx.y selects which W / output.
// ---------------------------------------------------------------------------
__global__ void qkv_kernel(const float* __restrict__ x,
                           const float* __restrict__ Wq,
                           const float* __restrict__ Wk,
                           const float* __restrict__ Wv) {
    const float* W = (blockIdx.y == 0) ? Wq : (blockIdx.y == 1) ? Wk : Wv;
    float* out = g_QKV[blockIdx.y];

    __shared__ float xs[64][33];                 // 64 rows x 32 k (scalar access)
    __shared__ __align__(16) float ws[32][STR];  // 32 k x 64 cols (float4 access)

    const int tid = threadIdx.x;
    const int tx = tid & 15;        // 0..15 -> output cols tx*4 .. tx*4+3
    const int ty = tid >> 4;        // 0..15 -> output rows ty*4 .. ty*4+3
    const int r0 = blockIdx.x * 64;

    float acc[4][4] = {};

    for (int kc = 0; kc < DIN; kc += 32) {
        __syncthreads();
        #pragma unroll
        for (int i = tid; i < 64 * 32; i += 256) {
            int r = i >> 5, k = i & 31;
            xs[r][k] = x[(r0 + r) * DIN + kc + k];
        }
        #pragma unroll
        for (int i = tid; i < 32 * 64; i += 256) {
            int k = i >> 6, c = i & 63;
            ws[k][c] = W[(kc + k) * D + c];
        }
        __syncthreads();

        #pragma unroll
        for (int k = 0; k < 32; k++) {
            float4 wv = *(const float4*)&ws[k][tx * 4];
            #pragma unroll
            for (int i = 0; i < 4; i++) {
                float xv = xs[ty * 4 + i][k];
                acc[i][0] += xv * wv.x;
                acc[i][1] += xv * wv.y;
                acc[i][2] += xv * wv.z;
                acc[i][3] += xv * wv.w;
            }
        }
    }

    #pragma unroll
    for (int i = 0; i < 4; i++)
        #pragma unroll
        for (int j = 0; j < 4; j++)
            out[(r0 + ty * 4 + i) * D + tx * 4 + j] = acc[i][j];
}

// ---------------------------------------------------------------------------
// Kernel 2: flash attention, fp32.
// BM=64 query rows per CTA, loop over key tiles of BN=64.
// Thread (ty,tx): rows ty*4+i (i=0..3), cols tx+16*j (j=0..3).
// The col mapping tx+16*j makes the K-tile float4 loads (consecutive rows
// across lanes, row stride 68 -> bank shift 4) conflict-free.
// Dynamic smem: Qs,Ks,Vs,Ps each [64][68] floats = 69632 B total.
// ---------------------------------------------------------------------------
__global__ void attn_kernel(float* __restrict__ out) {
    extern __shared__ __align__(16) float sm[];
    float* Qs = sm;                 // [64][STR]
    float* Ks = Qs + 64 * STR;
    float* Vs = Ks + 64 * STR;
    float* Ps = Vs + 64 * STR;

    const float* __restrict__ Q = g_QKV[0];
    const float* __restrict__ K = g_QKV[1];
    const float* __restrict__ V = g_QKV[2];

    const int tid = threadIdx.x;
    const int tx = tid & 15;
    const int ty = tid >> 4;
    const int r0 = blockIdx.x * BM;

    // Load Q tile, pre-scaled by 1/sqrt(64) = 0.125 (exact)
    #pragma unroll
    for (int i = tid; i < BM * D; i += 256) {
        int r = i >> 6, c = i & 63;
        Qs[r * STR + c] = Q[(r0 + r) * D + c] * 0.125f;
    }

    float m[4], l[4], acc[4][4];
    #pragma unroll
    for (int i = 0; i < 4; i++) {
        m[i] = -INFINITY; l[i] = 0.0f;
        #pragma unroll
        for (int j = 0; j < 4; j++) acc[i][j] = 0.0f;
    }
    __syncthreads();

    for (int kt = 0; kt < SEQ; kt += BN) {
        // Load K,V tiles (coalesced; previous iter's reads fenced by the
        // trailing __syncthreads of the loop body)
        #pragma unroll
        for (int i = tid; i < BN * D; i += 256) {
            int r = i >> 6, c = i & 63;
            Ks[r * STR + c] = K[(kt + r) * D + c];
            Vs[r * STR + c] = V[(kt + r) * D + c];
        }
        __syncthreads();

        // S[i][j] = Qs[row_i] . Ks[col_j]   (col_j = tx + 16*j)
        float S[4][4] = {};
        #pragma unroll
        for (int kk = 0; kk < D; kk += 4) {
            float4 q4[4], k4[4];
            #pragma unroll
            for (int i = 0; i < 4; i++)
                q4[i] = *(const float4*)&Qs[(ty * 4 + i) * STR + kk];
            #pragma unroll
            for (int j = 0; j < 4; j++)
                k4[j] = *(const float4*)&Ks[(tx + 16 * j) * STR + kk];
            #pragma unroll
            for (int i = 0; i < 4; i++)
                #pragma unroll
                for (int j = 0; j < 4; j++)
                    S[i][j] += q4[i].x * k4[j].x + q4[i].y * k4[j].y
                             + q4[i].z * k4[j].z + q4[i].w * k4[j].w;
        }

        // Online softmax update (row reductions across the 16 tx lanes)
        #pragma unroll
        for (int i = 0; i < 4; i++) {
            float mx = S[i][0];
            #pragma unroll
            for (int j = 1; j < 4; j++) mx = fmaxf(mx, S[i][j]);
            #pragma unroll
            for (int o = 1; o < 16; o <<= 1)
                mx = fmaxf(mx, __shfl_xor_sync(0xffffffffu, mx, o));
            float mnew = fmaxf(m[i], mx);
            float corr = __expf(m[i] - mnew);
            float rs = 0.0f;
            #pragma unroll
            for (int j = 0; j < 4; j++) {
                float p = __expf(S[i][j] - mnew);
                S[i][j] = p;
                rs += p;
            }
            #pragma unroll
            for (int o = 1; o < 16; o <<= 1)
                rs += __shfl_xor_sync(0xffffffffu, rs, o);
            l[i] = l[i] * corr + rs;
            m[i] = mnew;
            #pragma unroll
            for (int j = 0; j < 4; j++) acc[i][j] *= corr;
        }

        // Stage P to smem (P[row][key], key = tx+16*j)
        #pragma unroll
        for (int i = 0; i < 4; i++)
            #pragma unroll
            for (int j = 0; j < 4; j++)
                Ps[(ty * 4 + i) * STR + tx + 16 * j] = S[i][j];
        __syncthreads();

        // acc += P @ V ; acc cols = tx+16*jc
        #pragma unroll 4
        for (int kj = 0; kj < BN; kj += 4) {
            float4 p4[4];
            #pragma unroll
            for (int i = 0; i < 4; i++)
                p4[i] = *(const float4*)&Ps[(ty * 4 + i) * STR + kj];
            #pragma unroll
            for (int u = 0; u < 4; u++) {       // 4 keys in this quad
                float vv[4];
                #pragma unroll
                for (int jc = 0; jc < 4; jc++)
                    vv[jc] = Vs[(kj + u) * STR + tx + 16 * jc];
                const float pv[4] = {p4[0].x, p4[1].x, p4[2].x, p4[3].x};
                // select u-th component
                float pu[4];
                pu[0] = (u == 0) ? p4[0].x : (u == 1) ? p4[0].y : (u == 2) ? p4[0].z : p4[0].w;
                pu[1] = (u == 0) ? p4[1].x : (u == 1) ? p4[1].y : (u == 2) ? p4[1].z : p4[1].w;
                pu[2] = (u == 0) ? p4[2].x : (u == 1) ? p4[2].y : (u == 2) ? p4[2].z : p4[2].w;
                pu[3] = (u == 0) ? p4[3].x : (u == 1) ? p4[3].y : (u == 2) ? p4[3].z : p4[3].w;
                (void)pv;
                #pragma unroll
                for (int i = 0; i < 4; i++)
                    #pragma unroll
                    for (int jc = 0; jc < 4; jc++)
                        acc[i][jc] += pu[i] * vv[jc];
            }
        }
        __syncthreads();
    }

    // Normalize and write out
    #pragma unroll
    for (int i = 0; i < 4; i++) {
        float inv = 1.0f / l[i];
        #pragma unroll
        for (int j = 0; j < 4; j++)
            out[(r0 + ty * 4 + i) * D + tx + 16 * j] = acc[i][j] * inv;
    }
}

// ---------------------------------------------------------------------------
// Host launcher (graph-capturable: kernel launches + one attribute set only)
// ---------------------------------------------------------------------------
extern "C" void kernel_launch(void* const* d_in, const int* in_sizes, int n_in,
                              void* d_out, int out_size) {
    const float* x  = (const float*)d_in[0];
    const float* Wq = (const float*)d_in[1];
    const float* Wk = (const float*)d_in[2];
    const float* Wv = (const float*)d_in[3];
    float* out = (float*)d_out;

    const int attn_smem = 4 * 64 * STR * (int)sizeof(float);  // 69632 B
    cudaFuncSetAttribute(attn_kernel,
                         cudaFuncAttributeMaxDynamicSharedMemorySize, attn_smem);

    qkv_kernel<<<dim3(SEQ / 64, 3), 256>>>(x, Wq, Wk, Wv);
    attn_kernel<<<SEQ / BM, 256, attn_smem>>>(out);
}

// round 3
// speedup vs baseline: 2.0875x; 2.0875x over previous
#include <cuda_runtime.h>
#include <cuda_bf16.h>
#include <cstdint>
#include <math.h>

#define SEQ 8192
#define DIN 512
#define D   64
#define BN  64
#define NSPLIT 2
#define KPS (SEQ / NSPLIT)
#define KSTR 68
#define VSTR 72
#define QK_SCALE 0.18033688011112042f   // 0.125 * log2(e)

// ---------------- device scratch (no cudaMalloc allowed) ----------------
__device__ float g_qs[SEQ * D];               // Q, pre-scaled by 0.125*log2e
__device__ float g_ks[SEQ * D];               // K fp32
__device__ __nv_bfloat16 g_vth[D * SEQ];      // V^T bf16 hi   [dv][seq]
__device__ __nv_bfloat16 g_vtl[D * SEQ];      // V^T bf16 lo
__device__ float g_po[NSPLIT][SEQ * D];       // split-KV partial O (unnormalized)
__device__ float g_pm[NSPLIT][SEQ];           // partial row max (base-2 domain)
__device__ float g_pl[NSPLIT][SEQ];           // partial row sum

// ---------------- helpers ----------------
__device__ __forceinline__ float ex2(float x) {
    float r; asm("ex2.approx.f32 %0, %1;" : "=f"(r) : "f"(x)); return r;
}
__device__ __forceinline__ void tf32split(float x, uint32_t& h, uint32_t& l) {
    asm("cvt.rna.tf32.f32 %0, %1;" : "=r"(h) : "f"(x));
    float hf = __uint_as_float(h);
    asm("cvt.rna.tf32.f32 %0, %1;" : "=r"(l) : "f"(x - hf));
}
__device__ __forceinline__ void mma_tf32(float* c, const uint32_t* a,
                                         uint32_t b0, uint32_t b1) {
    asm volatile(
        "mma.sync.aligned.m16n8k8.row.col.f32.tf32.tf32.f32 "
        "{%0,%1,%2,%3},{%4,%5,%6,%7},{%8,%9},{%0,%1,%2,%3};"
        : "+f"(c[0]), "+f"(c[1]), "+f"(c[2]), "+f"(c[3])
        : "r"(a[0]), "r"(a[1]), "r"(a[2]), "r"(a[3]), "r"(b0), "r"(b1));
}
__device__ __forceinline__ void mma_bf16(float* c, const uint32_t* a,
                                         uint32_t b0, uint32_t b1) {
    asm volatile(
        "mma.sync.aligned.m16n8k16.row.col.f32.bf16.bf16.f32 "
        "{%0,%1,%2,%3},{%4,%5,%6,%7},{%8,%9},{%0,%1,%2,%3};"
        : "+f"(c[0]), "+f"(c[1]), "+f"(c[2]), "+f"(c[3])
        : "r"(a[0]), "r"(a[1]), "r"(a[2]), "r"(a[3]), "r"(b0), "r"(b1));
}
// pack (v0 -> low half, v1 -> high half) bf16 hi + residual lo
__device__ __forceinline__ void bsplit2(float v0, float v1, uint32_t& h, uint32_t& l) {
    __nv_bfloat16 h0 = __float2bfloat16(v0), h1 = __float2bfloat16(v1);
    float l0 = v0 - __bfloat162float(h0), l1 = v1 - __bfloat162float(h1);
    __nv_bfloat162 hh(h0, h1);
    __nv_bfloat162 ll(__float2bfloat16(l0), __float2bfloat16(l1));
    h = *(uint32_t*)&hh;
    l = *(uint32_t*)&ll;
}

// ---------------------------------------------------------------------------
// Kernel 1: QKV projection.  Q scaled fp32, K fp32, V transposed bf16 hi/lo.
// ---------------------------------------------------------------------------
__global__ void qkv_kernel(const float* __restrict__ x,
                           const float* __restrict__ Wq,
                           const float* __restrict__ Wk,
                           const float* __restrict__ Wv) {
    const float* W = (blockIdx.y == 0) ? Wq : (blockIdx.y == 1) ? Wk : Wv;

    __shared__ float xs[64][33];
    __shared__ __align__(16) float ws[32][68];

    const int tid = threadIdx.x;
    const int tx = tid & 15, ty = tid >> 4;
    const int r0 = blockIdx.x * 64;

    float acc[4][4] = {};
    for (int kc = 0; kc < DIN; kc += 32) {
        __syncthreads();
        for (int i = tid; i < 64 * 32; i += 256) {
            int r = i >> 5, k = i & 31;
            xs[r][k] = x[(r0 + r) * DIN + kc + k];
        }
        for (int i = tid; i < 32 * 64; i += 256) {
            int k = i >> 6, c = i & 63;
            ws[k][c] = W[(kc + k) * D + c];
        }
        __syncthreads();
        #pragma unroll
        for (int k = 0; k < 32; k++) {
            float4 wv = *(const float4*)&ws[k][tx * 4];
            #pragma unroll
            for (int i = 0; i < 4; i++) {
                float xv = xs[ty * 4 + i][k];
                acc[i][0] += xv * wv.x; acc[i][1] += xv * wv.y;
                acc[i][2] += xv * wv.z; acc[i][3] += xv * wv.w;
            }
        }
    }

    #pragma unroll
    for (int i = 0; i < 4; i++)
        #pragma unroll
        for (int j = 0; j < 4; j++) {
            int R = r0 + ty * 4 + i, C = tx * 4 + j;
            float v = acc[i][j];
            if (blockIdx.y == 0) {
                g_qs[R * D + C] = v * QK_SCALE;
            } else if (blockIdx.y == 1) {
                g_ks[R * D + C] = v;
            } else {
                __nv_bfloat16 h = __float2bfloat16(v);
                g_vth[C * SEQ + R] = h;
                g_vtl[C * SEQ + R] = __float2bfloat16(v - __bfloat162float(h));
            }
        }
}

// ---------------------------------------------------------------------------
// Kernel 2: flash attention via mma.sync.  grid (SEQ/64, NSPLIT), 128 threads.
// Warp w owns rows w*16..w*16+15.  QK = 3xTF32, PV = 3x bf16-split.
// ---------------------------------------------------------------------------
#define ATTN_SMEM (2 * BN * KSTR * 4 + 2 * D * VSTR * 2)   // 53248 B

__global__ __launch_bounds__(128, 2) void attn_kernel() {
    extern __shared__ char smc[];
    float* ksh = (float*)smc;
    float* ksl = ksh + BN * KSTR;
    __nv_bfloat16* vth = (__nv_bfloat16*)(ksl + BN * KSTR);
    __nv_bfloat16* vtl = vth + D * VSTR;

    const int tid = threadIdx.x, w = tid >> 5, lane = tid & 31;
    const int g = lane >> 2, t = lane & 3;
    const int r0 = blockIdx.x * 64;
    const int s = blockIdx.y;

    // ---- stage Q tile, build per-warp tf32 A-fragments (held in regs) ----
    for (int i = tid; i < 64 * 16; i += 128) {
        int r = i >> 4, cq = i & 15;
        *(float4*)&ksh[r * KSTR + cq * 4] = *(const float4*)&g_qs[(r0 + r) * D + cq * 4];
    }
    __syncthreads();
    uint32_t qh[8][4], ql[8][4];
    #pragma unroll
    for (int kc = 0; kc < 8; kc++)
        #pragma unroll
        for (int idx = 0; idx < 4; idx++) {
            int row = w * 16 + g + (idx & 1) * 8;
            int col = kc * 8 + t + (idx >> 1) * 4;
            tf32split(ksh[row * KSTR + col], qh[kc][idx], ql[kc][idx]);
        }
    __syncthreads();

    float o[8][4];
    #pragma unroll
    for (int nf = 0; nf < 8; nf++)
        #pragma unroll
        for (int i = 0; i < 4; i++) o[nf][i] = 0.0f;
    float m_a = -INFINITY, m_b = -INFINITY, l_a = 0.0f, l_b = 0.0f;

    for (int tt = 0; tt < KPS / BN; tt++) {
        const int kt = s * KPS + tt * BN;

        // ---- load K tile (fp32 -> tf32 hi/lo) and V^T tiles (bf16) ----
        for (int i = tid; i < 64 * 16; i += 128) {
            int r = i >> 4, cq = i & 15;
            float4 v = *(const float4*)&g_ks[(kt + r) * D + cq * 4];
            uint32_t h0, l0, h1, l1, h2, l2, h3, l3;
            tf32split(v.x, h0, l0); tf32split(v.y, h1, l1);
            tf32split(v.z, h2, l2); tf32split(v.w, h3, l3);
            *(float4*)&ksh[r * KSTR + cq * 4] =
                make_float4(__uint_as_float(h0), __uint_as_float(h1),
                            __uint_as_float(h2), __uint_as_float(h3));
            *(float4*)&ksl[r * KSTR + cq * 4] =
                make_float4(__uint_as_float(l0), __uint_as_float(l1),
                            __uint_as_float(l2), __uint_as_float(l3));
        }
        for (int i = tid; i < 64 * 8; i += 128) {
            int rv = i >> 3, cq = i & 7;
            *(uint4*)&vth[rv * VSTR + cq * 8] = *(const uint4*)&g_vth[rv * SEQ + kt + cq * 8];
            *(uint4*)&vtl[rv * VSTR + cq * 8] = *(const uint4*)&g_vtl[rv * SEQ + kt + cq * 8];
        }
        __syncthreads();

        // ---- S = Q K^T (3xTF32) ----
        float s_[8][4];
        #pragma unroll
        for (int j = 0; j < 8; j++)
            #pragma unroll
            for (int i = 0; i < 4; i++) s_[j][i] = 0.0f;

        #pragma unroll
        for (int j = 0; j < 8; j++) {
            const float* kb  = &ksh[(j * 8 + g) * KSTR];
            const float* kbl = &ksl[(j * 8 + g) * KSTR];
            #pragma unroll
            for (int kc = 0; kc < 8; kc++) {
                uint32_t bh0 = __float_as_uint(kb[kc * 8 + t]);
                uint32_t bh1 = __float_as_uint(kb[kc * 8 + t + 4]);
                uint32_t bl0 = __float_as_uint(kbl[kc * 8 + t]);
                uint32_t bl1 = __float_as_uint(kbl[kc * 8 + t + 4]);
                mma_tf32(s_[j], qh[kc], bh0, bh1);
                mma_tf32(s_[j], ql[kc], bh0, bh1);
                mma_tf32(s_[j], qh[kc], bl0, bl1);
            }
        }

        // ---- online softmax (base-2 domain) ----
        float mxa = -INFINITY, mxb = -INFINITY;
        #pragma unroll
        for (int j = 0; j < 8; j++) {
            mxa = fmaxf(mxa, fmaxf(s_[j][0], s_[j][1]));
            mxb = fmaxf(mxb, fmaxf(s_[j][2], s_[j][3]));
        }
        mxa = fmaxf(mxa, __shfl_xor_sync(0xffffffffu, mxa, 1));
        mxa = fmaxf(mxa, __shfl_xor_sync(0xffffffffu, mxa, 2));
        mxb = fmaxf(mxb, __shfl_xor_sync(0xffffffffu, mxb, 1));
        mxb = fmaxf(mxb, __shfl_xor_sync(0xffffffffu, mxb, 2));
        float mna = fmaxf(m_a, mxa), mnb = fmaxf(m_b, mxb);
        float ca = ex2(m_a - mna), cb = ex2(m_b - mnb);
        m_a = mna; m_b = mnb;
        float ra = 0.0f, rb = 0.0f;
        #pragma unroll
        for (int j = 0; j < 8; j++) {
            s_[j][0] = ex2(s_[j][0] - m_a);
            s_[j][1] = ex2(s_[j][1] - m_a);
            s_[j][2] = ex2(s_[j][2] - m_b);
            s_[j][3] = ex2(s_[j][3] - m_b);
            ra += s_[j][0] + s_[j][1];
            rb += s_[j][2] + s_[j][3];
        }
        l_a = l_a * ca + ra;        // per-lane partial; reduced at the end
        l_b = l_b * cb + rb;
        #pragma unroll
        for (int nf = 0; nf < 8; nf++) {
            o[nf][0] *= ca; o[nf][1] *= ca;
            o[nf][2] *= cb; o[nf][3] *= cb;
        }

        // ---- pack P into bf16 hi/lo A-fragments (register-only) ----
        uint32_t ah[4][4], al[4][4];
        #pragma unroll
        for (int kk = 0; kk < 4; kk++) {
            int j0 = 2 * kk, j1 = 2 * kk + 1;
            bsplit2(s_[j0][0], s_[j0][1], ah[kk][0], al[kk][0]);
            bsplit2(s_[j0][2], s_[j0][3], ah[kk][1], al[kk][1]);
            bsplit2(s_[j1][0], s_[j1][1], ah[kk][2], al[kk][2]);
            bsplit2(s_[j1][2], s_[j1][3], ah[kk][3], al[kk][3]);
        }

        // ---- O += P V (bf16, 3 passes) ----
        #pragma unroll
        for (int nf = 0; nf < 8; nf++) {
            const __nv_bfloat16* vb  = &vth[(nf * 8 + g) * VSTR];
            const __nv_bfloat16* vbl = &vtl[(nf * 8 + g) * VSTR];
            #pragma unroll
            for (int kk = 0; kk < 4; kk++) {
                uint32_t bh0 = *(const uint32_t*)&vb[kk * 16 + 2 * t];
                uint32_t bh1 = *(const uint32_t*)&vb[kk * 16 + 2 * t + 8];
                uint32_t bl0 = *(const uint32_t*)&vbl[kk * 16 + 2 * t];
                uint32_t bl1 = *(const uint32_t*)&vbl[kk * 16 + 2 * t + 8];
                mma_bf16(o[nf], ah[kk], bh0, bh1);
                mma_bf16(o[nf], ah[kk], bl0, bl1);
                mma_bf16(o[nf], al[kk], bh0, bh1);
            }
        }
        __syncthreads();
    }

    // ---- finalize: reduce l across quad, store partials ----
    l_a += __shfl_xor_sync(0xffffffffu, l_a, 1);
    l_a += __shfl_xor_sync(0xffffffffu, l_a, 2);
    l_b += __shfl_xor_sync(0xffffffffu, l_b, 1);
    l_b += __shfl_xor_sync(0xffffffffu, l_b, 2);

    const int rowA = r0 + w * 16 + g, rowB = rowA + 8;
    #pragma unroll
    for (int nf = 0; nf < 8; nf++) {
        g_po[s][rowA * D + nf * 8 + 2 * t]     = o[nf][0];
        g_po[s][rowA * D + nf * 8 + 2 * t + 1] = o[nf][1];
        g_po[s][rowB * D + nf * 8 + 2 * t]     = o[nf][2];
        g_po[s][rowB * D + nf * 8 + 2 * t + 1] = o[nf][3];
    }
    if (t == 0) {
        g_pm[s][rowA] = m_a; g_pl[s][rowA] = l_a;
        g_pm[s][rowB] = m_b; g_pl[s][rowB] = l_b;
    }
}

// ---------------------------------------------------------------------------
// Kernel 3: combine the two KV splits.
// ---------------------------------------------------------------------------
__global__ void combine_kernel(float* __restrict__ out) {
    int idx = blockIdx.x * 256 + threadIdx.x;
    int r = idx >> 6;
    float m0 = g_pm[0][r], m1 = g_pm[1][r];
    float M = fmaxf(m0, m1);
    float w0 = ex2(m0 - M), w1 = ex2(m1 - M);
    out[idx] = (g_po[0][idx] * w0 + g_po[1][idx] * w1)
             / (g_pl[0][r] * w0 + g_pl[1][r] * w1);
}

// ---------------------------------------------------------------------------
extern "C" void kernel_launch(void* const* d_in, const int* in_sizes, int n_in,
                              void* d_out, int out_size) {
    const float* x  = (const float*)d_in[0];
    const float* Wq = (const float*)d_in[1];
    const float* Wk = (const float*)d_in[2];
    const float* Wv = (const float*)d_in[3];
    float* out = (float*)d_out;

    cudaFuncSetAttribute(attn_kernel,
                         cudaFuncAttributeMaxDynamicSharedMemorySize, ATTN_SMEM);

    qkv_kernel<<<dim3(SEQ / 64, 3), 256>>>(x, Wq, Wk, Wv);
    attn_kernel<<<dim3(SEQ / 64, NSPLIT), 128, ATTN_SMEM>>>();
    combine_kernel<<<(SEQ * D) / 256, 256>>>(out);
}

// round 4
// speedup vs baseline: 3.6920x; 1.7686x over previous
#include <cuda_runtime.h>
#include <cuda_bf16.h>
#include <cstdint>
#include <math.h>

#define SEQ 8192
#define DIN 512
#define D   64
#define BN  64
#define NSPLIT 2
#define KPS (SEQ / NSPLIT)
#define QK_SCALE 0.18033688011112042f   // 0.125 * log2(e)
#define XS  36      // qkv smem row stride (floats)
#define KST 72      // attn smem row stride (bf16)

// ---------------- device scratch (no cudaMalloc allowed) ----------------
__device__ float g_wth[3][D * DIN];          // W^T tf32 hi  [n*DIN + k]
__device__ float g_wtl[3][D * DIN];          // W^T tf32 lo
__device__ __nv_bfloat16 g_qh[SEQ * D], g_ql[SEQ * D];   // Q bf16 hi/lo (scaled)
__device__ __nv_bfloat16 g_kh[SEQ * D], g_kl[SEQ * D];   // K bf16 hi/lo
__device__ __nv_bfloat16 g_vh[D * SEQ], g_vl[D * SEQ];   // V^T bf16 hi/lo
__device__ float g_po[NSPLIT][SEQ * D];
__device__ float g_pm[NSPLIT][SEQ];
__device__ float g_pl[NSPLIT][SEQ];

// ---------------- helpers ----------------
__device__ __forceinline__ float ex2(float x) {
    float r; asm("ex2.approx.f32 %0, %1;" : "=f"(r) : "f"(x)); return r;
}
__device__ __forceinline__ void tf32split(float x, uint32_t& h, uint32_t& l) {
    asm("cvt.rna.tf32.f32 %0, %1;" : "=r"(h) : "f"(x));
    float hf = __uint_as_float(h);
    asm("cvt.rna.tf32.f32 %0, %1;" : "=r"(l) : "f"(x - hf));
}
__device__ __forceinline__ void mma_tf32(float* c, const uint32_t* a,
                                         uint32_t b0, uint32_t b1) {
    asm volatile(
        "mma.sync.aligned.m16n8k8.row.col.f32.tf32.tf32.f32 "
        "{%0,%1,%2,%3},{%4,%5,%6,%7},{%8,%9},{%0,%1,%2,%3};"
        : "+f"(c[0]), "+f"(c[1]), "+f"(c[2]), "+f"(c[3])
        : "r"(a[0]), "r"(a[1]), "r"(a[2]), "r"(a[3]), "r"(b0), "r"(b1));
}
__device__ __forceinline__ void mma_bf16(float* c, const uint32_t* a,
                                         uint32_t b0, uint32_t b1) {
    asm volatile(
        "mma.sync.aligned.m16n8k16.row.col.f32.bf16.bf16.f32 "
        "{%0,%1,%2,%3},{%4,%5,%6,%7},{%8,%9},{%0,%1,%2,%3};"
        : "+f"(c[0]), "+f"(c[1]), "+f"(c[2]), "+f"(c[3])
        : "r"(a[0]), "r"(a[1]), "r"(a[2]), "r"(a[3]), "r"(b0), "r"(b1));
}
__device__ __forceinline__ uint32_t pack_bf16(float lo, float hi) {
    uint32_t r;
    asm("cvt.rn.bf16x2.f32 %0, %1, %2;" : "=r"(r) : "f"(hi), "f"(lo));
    return r;
}
// bf16 hi/lo split of pair (v0->low half, v1->high half)
__device__ __forceinline__ void bsplit2(float v0, float v1, uint32_t& h, uint32_t& l) {
    __nv_bfloat16 h0 = __float2bfloat16(v0), h1 = __float2bfloat16(v1);
    float l0 = v0 - __bfloat162float(h0), l1 = v1 - __bfloat162float(h1);
    __nv_bfloat162 hh(h0, h1);
    __nv_bfloat162 ll(__float2bfloat16(l0), __float2bfloat16(l1));
    h = *(uint32_t*)&hh;
    l = *(uint32_t*)&ll;
}
__device__ __forceinline__ uint32_t smem_u32(const void* p) {
    uint32_t a;
    asm("{ .reg .u64 t; cvta.to.shared.u64 t, %1; cvt.u32.u64 %0, t; }" : "=r"(a) : "l"(p));
    return a;
}
__device__ __forceinline__ void cp16(uint32_t dst, const void* src) {
    asm volatile("cp.async.cg.shared.global [%0], [%1], 16;" :: "r"(dst), "l"(src) : "memory");
}
#define CP_COMMIT() asm volatile("cp.async.commit_group;" ::: "memory")
#define CP_WAIT0()  asm volatile("cp.async.wait_group 0;" ::: "memory")

// ---------------------------------------------------------------------------
// Kernel 0: split the three W matrices into tf32 hi/lo, transposed.
// ---------------------------------------------------------------------------
__global__ void prep_kernel(const float* __restrict__ Wq,
                            const float* __restrict__ Wk,
                            const float* __restrict__ Wv) {
    int i = blockIdx.x * 256 + threadIdx.x;          // < 3*D*DIN
    int p = i / (D * DIN), r = i % (D * DIN);
    int n = r / DIN, k = r % DIN;
    const float* W = (p == 0) ? Wq : (p == 1) ? Wk : Wv;
    float w = W[k * D + n];
    uint32_t h, l;
    tf32split(w, h, l);
    g_wth[p][n * DIN + k] = __uint_as_float(h);
    g_wtl[p][n * DIN + k] = __uint_as_float(l);
}

// ---------------------------------------------------------------------------
// Kernel 1: QKV projection via tf32 mma (3-pass).  grid (SEQ/128, 3), 256 thr.
// Outputs pre-split bf16 hi/lo (Q scaled; V transposed).
// ---------------------------------------------------------------------------
#define QKV_SMEM ((128 * XS * 2 + 64 * XS * 2) * 4)   // 55296 B

__global__ __launch_bounds__(256, 2) void qkv_kernel(const float* __restrict__ x) {
    extern __shared__ float qsm[];
    float* xh = qsm;                 // [128][XS]
    float* xl = xh + 128 * XS;
    float* wh = xl + 128 * XS;       // [64][XS]
    float* wl = wh + 64 * XS;

    const int tid = threadIdx.x, w = tid >> 5, lane = tid & 31;
    const int g = lane >> 2, t = lane & 3;
    const int r0 = blockIdx.x * 128;
    const int p = blockIdx.y;
    const float* wth = g_wth[p];
    const float* wtl = g_wtl[p];

    float c[8][4];
    #pragma unroll
    for (int nf = 0; nf < 8; nf++)
        #pragma unroll
        for (int i = 0; i < 4; i++) c[nf][i] = 0.0f;

    for (int kb = 0; kb < DIN; kb += 32) {
        __syncthreads();
        // x tile 128x32 -> tf32 hi/lo
        #pragma unroll
        for (int i = tid; i < 1024; i += 256) {
            int r = i >> 3, c4 = i & 7;
            float4 v = *(const float4*)&x[(r0 + r) * DIN + kb + c4 * 4];
            uint32_t h0, l0, h1, l1, h2, l2, h3, l3;
            tf32split(v.x, h0, l0); tf32split(v.y, h1, l1);
            tf32split(v.z, h2, l2); tf32split(v.w, h3, l3);
            *(float4*)&xh[r * XS + c4 * 4] =
                make_float4(__uint_as_float(h0), __uint_as_float(h1),
                            __uint_as_float(h2), __uint_as_float(h3));
            *(float4*)&xl[r * XS + c4 * 4] =
                make_float4(__uint_as_float(l0), __uint_as_float(l1),
                            __uint_as_float(l2), __uint_as_float(l3));
        }
        // W chunk 64x32 (pre-split)
        #pragma unroll
        for (int i = tid; i < 512; i += 256) {
            int n = i >> 3, c4 = i & 7;
            *(float4*)&wh[n * XS + c4 * 4] = *(const float4*)&wth[n * DIN + kb + c4 * 4];
            *(float4*)&wl[n * XS + c4 * 4] = *(const float4*)&wtl[n * DIN + kb + c4 * 4];
        }
        __syncthreads();

        #pragma unroll
        for (int kc = 0; kc < 4; kc++) {
            const int ra = w * 16 + g, k0 = kc * 8 + t;
            uint32_t ah[4], al[4];
            ah[0] = __float_as_uint(xh[ra * XS + k0]);
            ah[1] = __float_as_uint(xh[(ra + 8) * XS + k0]);
            ah[2] = __float_as_uint(xh[ra * XS + k0 + 4]);
            ah[3] = __float_as_uint(xh[(ra + 8) * XS + k0 + 4]);
            al[0] = __float_as_uint(xl[ra * XS + k0]);
            al[1] = __float_as_uint(xl[(ra + 8) * XS + k0]);
            al[2] = __float_as_uint(xl[ra * XS + k0 + 4]);
            al[3] = __float_as_uint(xl[(ra + 8) * XS + k0 + 4]);
            #pragma unroll
            for (int nf = 0; nf < 8; nf++) {
                const int nr = nf * 8 + g;
                uint32_t bh0 = __float_as_uint(wh[nr * XS + kc * 8 + t]);
                uint32_t bh1 = __float_as_uint(wh[nr * XS + kc * 8 + t + 4]);
                uint32_t bl0 = __float_as_uint(wl[nr * XS + kc * 8 + t]);
                uint32_t bl1 = __float_as_uint(wl[nr * XS + kc * 8 + t + 4]);
                mma_tf32(c[nf], ah, bh0, bh1);
                mma_tf32(c[nf], al, bh0, bh1);
                mma_tf32(c[nf], ah, bl0, bl1);
            }
        }
    }

    // epilogue
    const int rowA = r0 + w * 16 + g, rowB = rowA + 8;
    if (p == 2) {
        #pragma unroll
        for (int nf = 0; nf < 8; nf++) {
            int c0 = nf * 8 + 2 * t;
            float vals[4] = {c[nf][0], c[nf][1], c[nf][2], c[nf][3]};
            int cols[4] = {c0, c0 + 1, c0, c0 + 1};
            int rows[4] = {rowA, rowA, rowB, rowB};
            #pragma unroll
            for (int q = 0; q < 4; q++) {
                __nv_bfloat16 h = __float2bfloat16(vals[q]);
                g_vh[cols[q] * SEQ + rows[q]] = h;
                g_vl[cols[q] * SEQ + rows[q]] =
                    __float2bfloat16(vals[q] - __bfloat162float(h));
            }
        }
    } else {
        __nv_bfloat16* dh = (p == 0) ? g_qh : g_kh;
        __nv_bfloat16* dl = (p == 0) ? g_ql : g_kl;
        const float sc = (p == 0) ? QK_SCALE : 1.0f;
        #pragma unroll
        for (int nf = 0; nf < 8; nf++) {
            uint32_t hA, lA, hB, lB;
            bsplit2(c[nf][0] * sc, c[nf][1] * sc, hA, lA);
            bsplit2(c[nf][2] * sc, c[nf][3] * sc, hB, lB);
            int off = nf * 8 + 2 * t;
            *(uint32_t*)&dh[rowA * D + off] = hA;
            *(uint32_t*)&dl[rowA * D + off] = lA;
            *(uint32_t*)&dh[rowB * D + off] = hB;
            *(uint32_t*)&dl[rowB * D + off] = lB;
        }
    }
}

// ---------------------------------------------------------------------------
// Kernel 2: flash attention.  grid (SEQ/64, NSPLIT), 128 threads.
// QK = bf16 2-split 3-pass (m16n8k16); PV = Ph x (Vh,Vl) 2-pass.
// ---------------------------------------------------------------------------
#define ATT_SMEM (4 * 64 * KST * 2)   // 36864 B

__global__ __launch_bounds__(128, 2) void attn_kernel() {
    extern __shared__ __nv_bfloat16 smb[];
    __nv_bfloat16* kh = smb;             // [64][KST]
    __nv_bfloat16* kl = kh + 64 * KST;
    __nv_bfloat16* vh = kl + 64 * KST;
    __nv_bfloat16* vl = vh + 64 * KST;

    const int tid = threadIdx.x, w = tid >> 5, lane = tid & 31;
    const int g = lane >> 2, t = lane & 3;
    const int r0 = blockIdx.x * 64;
    const int s = blockIdx.y;
    const uint32_t sbase = smem_u32(smb);

    // Q fragments (persist)
    const int rowA = r0 + w * 16 + g, rowB = rowA + 8;
    uint32_t qh[4][4], ql[4][4];
    #pragma unroll
    for (int kc = 0; kc < 4; kc++) {
        int k0 = kc * 16 + 2 * t;
        qh[kc][0] = *(const uint32_t*)&g_qh[rowA * D + k0];
        qh[kc][1] = *(const uint32_t*)&g_qh[rowB * D + k0];
        qh[kc][2] = *(const uint32_t*)&g_qh[rowA * D + k0 + 8];
        qh[kc][3] = *(const uint32_t*)&g_qh[rowB * D + k0 + 8];
        ql[kc][0] = *(const uint32_t*)&g_ql[rowA * D + k0];
        ql[kc][1] = *(const uint32_t*)&g_ql[rowB * D + k0];
        ql[kc][2] = *(const uint32_t*)&g_ql[rowA * D + k0 + 8];
        ql[kc][3] = *(const uint32_t*)&g_ql[rowB * D + k0 + 8];
    }

    float o[8][4];
    #pragma unroll
    for (int nf = 0; nf < 8; nf++)
        #pragma unroll
        for (int i = 0; i < 4; i++) o[nf][i] = 0.0f;
    float m_a = -INFINITY, m_b = -INFINITY, l_a = 0.0f, l_b = 0.0f;

    // tile loader: 2048 x 16B chunks (4 arrays x 64 rows x 128B)
    auto issue_tile = [&](int kt) {
        #pragma unroll
        for (int i = tid; i < 2048; i += 128) {
            int arr = i >> 9, rem = i & 511, r = rem >> 3, c8 = rem & 7;
            const __nv_bfloat16* src;
            if      (arr == 0) src = &g_kh[(kt + r) * D + c8 * 8];
            else if (arr == 1) src = &g_kl[(kt + r) * D + c8 * 8];
            else if (arr == 2) src = &g_vh[r * SEQ + kt + c8 * 8];
            else               src = &g_vl[r * SEQ + kt + c8 * 8];
            uint32_t dst = sbase + (uint32_t)(arr * 64 * KST + r * KST + c8 * 8) * 2u;
            cp16(dst, src);
        }
        CP_COMMIT();
    };

    issue_tile(s * KPS);

    for (int tt = 0; tt < KPS / BN; tt++) {
        CP_WAIT0();
        __syncthreads();

        // ---- S = Q K^T : bf16 3-pass ----
        float s_[8][4];
        #pragma unroll
        for (int j = 0; j < 8; j++)
            #pragma unroll
            for (int i = 0; i < 4; i++) s_[j][i] = 0.0f;
        #pragma unroll
        for (int j = 0; j < 8; j++) {
            const __nv_bfloat16* bh = &kh[(j * 8 + g) * KST];
            const __nv_bfloat16* bl = &kl[(j * 8 + g) * KST];
            #pragma unroll
            for (int kc = 0; kc < 4; kc++) {
                uint32_t b0 = *(const uint32_t*)&bh[kc * 16 + 2 * t];
                uint32_t b1 = *(const uint32_t*)&bh[kc * 16 + 2 * t + 8];
                uint32_t d0 = *(const uint32_t*)&bl[kc * 16 + 2 * t];
                uint32_t d1 = *(const uint32_t*)&bl[kc * 16 + 2 * t + 8];
                mma_bf16(s_[j], qh[kc], b0, b1);
                mma_bf16(s_[j], ql[kc], b0, b1);
                mma_bf16(s_[j], qh[kc], d0, d1);
            }
        }

        // ---- online softmax (base-2) ----
        float mxa = -INFINITY, mxb = -INFINITY;
        #pragma unroll
        for (int j = 0; j < 8; j++) {
            mxa = fmaxf(mxa, fmaxf(s_[j][0], s_[j][1]));
            mxb = fmaxf(mxb, fmaxf(s_[j][2], s_[j][3]));
        }
        mxa = fmaxf(mxa, __shfl_xor_sync(0xffffffffu, mxa, 1));
        mxa = fmaxf(mxa, __shfl_xor_sync(0xffffffffu, mxa, 2));
        mxb = fmaxf(mxb, __shfl_xor_sync(0xffffffffu, mxb, 1));
        mxb = fmaxf(mxb, __shfl_xor_sync(0xffffffffu, mxb, 2));
        float mna = fmaxf(m_a, mxa), mnb = fmaxf(m_b, mxb);
        float ca = ex2(m_a - mna), cb = ex2(m_b - mnb);
        m_a = mna; m_b = mnb;
        float ra = 0.0f, rb = 0.0f;
        #pragma unroll
        for (int j = 0; j < 8; j++) {
            s_[j][0] = ex2(s_[j][0] - m_a);
            s_[j][1] = ex2(s_[j][1] - m_a);
            s_[j][2] = ex2(s_[j][2] - m_b);
            s_[j][3] = ex2(s_[j][3] - m_b);
            ra += s_[j][0] + s_[j][1];
            rb += s_[j][2] + s_[j][3];
        }
        l_a = l_a * ca + ra;
        l_b = l_b * cb + rb;
        #pragma unroll
        for (int nf = 0; nf < 8; nf++) {
            o[nf][0] *= ca; o[nf][1] *= ca;
            o[nf][2] *= cb; o[nf][3] *= cb;
        }

        // ---- pack P (hi only) ----
        uint32_t ah[4][4];
        #pragma unroll
        for (int kk = 0; kk < 4; kk++) {
            ah[kk][0] = pack_bf16(s_[2 * kk][0], s_[2 * kk][1]);
            ah[kk][1] = pack_bf16(s_[2 * kk][2], s_[2 * kk][3]);
            ah[kk][2] = pack_bf16(s_[2 * kk + 1][0], s_[2 * kk + 1][1]);
            ah[kk][3] = pack_bf16(s_[2 * kk + 1][2], s_[2 * kk + 1][3]);
        }

        // ---- O += P V : 2 passes ----
        #pragma unroll
        for (int nf = 0; nf < 8; nf++) {
            const __nv_bfloat16* bh = &vh[(nf * 8 + g) * KST];
            const __nv_bfloat16* bl = &vl[(nf * 8 + g) * KST];
            #pragma unroll
            for (int kk = 0; kk < 4; kk++) {
                uint32_t b0 = *(const uint32_t*)&bh[kk * 16 + 2 * t];
                uint32_t b1 = *(const uint32_t*)&bh[kk * 16 + 2 * t + 8];
                uint32_t d0 = *(const uint32_t*)&bl[kk * 16 + 2 * t];
                uint32_t d1 = *(const uint32_t*)&bl[kk * 16 + 2 * t + 8];
                mma_bf16(o[nf], ah[kk], b0, b1);
                mma_bf16(o[nf], ah[kk], d0, d1);
            }
        }
        __syncthreads();
        if (tt + 1 < KPS / BN) issue_tile(s * KPS + (tt + 1) * BN);
    }

    // ---- finalize ----
    l_a += __shfl_xor_sync(0xffffffffu, l_a, 1);
    l_a += __shfl_xor_sync(0xffffffffu, l_a, 2);
    l_b += __shfl_xor_sync(0xffffffffu, l_b, 1);
    l_b += __shfl_xor_sync(0xffffffffu, l_b, 2);

    #pragma unroll
    for (int nf = 0; nf < 8; nf++) {
        g_po[s][rowA * D + nf * 8 + 2 * t]     = o[nf][0];
        g_po[s][rowA * D + nf * 8 + 2 * t + 1] = o[nf][1];
        g_po[s][rowB * D + nf * 8 + 2 * t]     = o[nf][2];
        g_po[s][rowB * D + nf * 8 + 2 * t + 1] = o[nf][3];
    }
    if (t == 0) {
        g_pm[s][rowA] = m_a; g_pl[s][rowA] = l_a;
        g_pm[s][rowB] = m_b; g_pl[s][rowB] = l_b;
    }
}

// ---------------------------------------------------------------------------
// Kernel 3: combine the two KV splits.
// ---------------------------------------------------------------------------
__global__ void combine_kernel(float* __restrict__ out) {
    int idx = blockIdx.x * 256 + threadIdx.x;
    int r = idx >> 6;
    float m0 = g_pm[0][r], m1 = g_pm[1][r];
    float M = fmaxf(m0, m1);
    float w0 = ex2(m0 - M), w1 = ex2(m1 - M);
    out[idx] = (g_po[0][idx] * w0 + g_po[1][idx] * w1)
             / (g_pl[0][r] * w0 + g_pl[1][r] * w1);
}

// ---------------------------------------------------------------------------
extern "C" void kernel_launch(void* const* d_in, const int* in_sizes, int n_in,
                              void* d_out, int out_size) {
    const float* x  = (const float*)d_in[0];
    const float* Wq = (const float*)d_in[1];
    const float* Wk = (const float*)d_in[2];
    const float* Wv = (const float*)d_in[3];
    float* out = (float*)d_out;

    cudaFuncSetAttribute(qkv_kernel,
                         cudaFuncAttributeMaxDynamicSharedMemorySize, QKV_SMEM);

    prep_kernel<<<(3 * D * DIN) / 256, 256>>>(Wq, Wk, Wv);
    qkv_kernel<<<dim3(SEQ / 128, 3), 256, QKV_SMEM>>>(x);
    attn_kernel<<<dim3(SEQ / 64, NSPLIT), 128, ATT_SMEM>>>();
    combine_kernel<<<(SEQ * D) / 256, 256>>>(out);
}

// round 5
// speedup vs baseline: 4.1421x; 1.1219x over previous
#include <cuda_runtime.h>
#include <cuda_bf16.h>
#include <cstdint>
#include <math.h>

#define SEQ 8192
#define DIN 512
#define D   64
#define BN  64
#define NSPLIT 16
#define TILES_PER_UNIT 8            // 8 * 64 = 512 keys per unit
#define TOTAL_UNITS (128 * NSPLIT)  // 2048
#define GRID_ATTN 296
#define QK_SCALE 0.18033688011112042f   // 0.125 * log2(e)
#define XSB 40      // qkv smem row stride (bf16)
#define KST 72      // attn smem row stride (bf16)
#define BUFB (4 * 64 * KST * 2)     // one attn buffer: 36864 B

// ---------------- device scratch (no cudaMalloc allowed) ----------------
__device__ __nv_bfloat16 g_wh[3][D * DIN], g_wl[3][D * DIN];   // W^T bf16 hi/lo
__device__ __nv_bfloat16 g_qh[SEQ * D], g_ql[SEQ * D];         // Q bf16 hi/lo (scaled)
__device__ __nv_bfloat16 g_kh[SEQ * D], g_kl[SEQ * D];         // K bf16 hi/lo
__device__ __nv_bfloat16 g_vh[D * SEQ], g_vl[D * SEQ];         // V^T bf16 hi/lo
__device__ float g_po[NSPLIT][SEQ * D];
__device__ float g_pm[NSPLIT][SEQ];
__device__ float g_pl[NSPLIT][SEQ];

// ---------------- helpers ----------------
__device__ __forceinline__ float ex2(float x) {
    float r; asm("ex2.approx.f32 %0, %1;" : "=f"(r) : "f"(x)); return r;
}
__device__ __forceinline__ void mma_bf16(float* c, const uint32_t* a,
                                         uint32_t b0, uint32_t b1) {
    asm volatile(
        "mma.sync.aligned.m16n8k16.row.col.f32.bf16.bf16.f32 "
        "{%0,%1,%2,%3},{%4,%5,%6,%7},{%8,%9},{%0,%1,%2,%3};"
        : "+f"(c[0]), "+f"(c[1]), "+f"(c[2]), "+f"(c[3])
        : "r"(a[0]), "r"(a[1]), "r"(a[2]), "r"(a[3]), "r"(b0), "r"(b1));
}
__device__ __forceinline__ uint32_t pack_bf16(float lo, float hi) {
    uint32_t r;
    asm("cvt.rn.bf16x2.f32 %0, %1, %2;" : "=r"(r) : "f"(hi), "f"(lo));
    return r;
}
// bf16 hi/lo split of pair (v0->low half, v1->high half)
__device__ __forceinline__ void bsplit2(float v0, float v1, uint32_t& h, uint32_t& l) {
    __nv_bfloat16 h0 = __float2bfloat16(v0), h1 = __float2bfloat16(v1);
    float l0 = v0 - __bfloat162float(h0), l1 = v1 - __bfloat162float(h1);
    __nv_bfloat162 hh(h0, h1);
    __nv_bfloat162 ll(__float2bfloat16(l0), __float2bfloat16(l1));
    h = *(uint32_t*)&hh;
    l = *(uint32_t*)&ll;
}
__device__ __forceinline__ uint32_t smem_u32(const void* p) {
    uint32_t a;
    asm("{ .reg .u64 t; cvta.to.shared.u64 t, %1; cvt.u32.u64 %0, t; }" : "=r"(a) : "l"(p));
    return a;
}
__device__ __forceinline__ void cp16(uint32_t dst, const void* src) {
    asm volatile("cp.async.cg.shared.global [%0], [%1], 16;" :: "r"(dst), "l"(src) : "memory");
}
#define CP_COMMIT() asm volatile("cp.async.commit_group;" ::: "memory")
#define CP_WAIT0()  asm volatile("cp.async.wait_group 0;" ::: "memory")

// ---------------------------------------------------------------------------
// Kernel 0: split W^T into bf16 hi/lo.
// ---------------------------------------------------------------------------
__global__ void prep_kernel(const float* __restrict__ Wq,
                            const float* __restrict__ Wk,
                            const float* __restrict__ Wv) {
    int i = blockIdx.x * 256 + threadIdx.x;          // < 3*D*DIN
    int p = i / (D * DIN), r = i % (D * DIN);
    int n = r / DIN, k = r % DIN;
    const float* W = (p == 0) ? Wq : (p == 1) ? Wk : Wv;
    float w = W[k * D + n];
    __nv_bfloat16 h = __float2bfloat16(w);
    g_wh[p][n * DIN + k] = h;
    g_wl[p][n * DIN + k] = __float2bfloat16(w - __bfloat162float(h));
}

// ---------------------------------------------------------------------------
// Kernel 1: QKV projection via bf16 2-split 3-pass mma.  grid (SEQ/128, 3).
// ---------------------------------------------------------------------------
#define QKV_SMEM ((128 * XSB * 2 + 64 * XSB * 2) * 2)   // 30720 B

__global__ __launch_bounds__(256, 2) void qkv_kernel(const float* __restrict__ x) {
    extern __shared__ __nv_bfloat16 qsm[];
    __nv_bfloat16* xh = qsm;                 // [128][XSB]
    __nv_bfloat16* xl = xh + 128 * XSB;
    __nv_bfloat16* wh = xl + 128 * XSB;      // [64][XSB]
    __nv_bfloat16* wl = wh + 64 * XSB;

    const int tid = threadIdx.x, w = tid >> 5, lane = tid & 31;
    const int g = lane >> 2, t = lane & 3;
    const int r0 = blockIdx.x * 128;
    const int p = blockIdx.y;

    float c[8][4];
    #pragma unroll
    for (int nf = 0; nf < 8; nf++)
        #pragma unroll
        for (int i = 0; i < 4; i++) c[nf][i] = 0.0f;

    for (int kb = 0; kb < DIN; kb += 32) {
        __syncthreads();
        // x tile 128x32 -> bf16 hi/lo
        #pragma unroll
        for (int i = tid; i < 1024; i += 256) {
            int r = i >> 3, c4 = i & 7;
            float4 v = *(const float4*)&x[(r0 + r) * DIN + kb + c4 * 4];
            uint32_t h0, l0, h1, l1;
            bsplit2(v.x, v.y, h0, l0);
            bsplit2(v.z, v.w, h1, l1);
            *(uint2*)&xh[r * XSB + c4 * 4] = make_uint2(h0, h1);
            *(uint2*)&xl[r * XSB + c4 * 4] = make_uint2(l0, l1);
        }
        // W chunk 64x32 (pre-split bf16)
        #pragma unroll
        for (int i = tid; i < 512; i += 256) {
            int n = i >> 3, c4 = i & 7;
            *(uint2*)&wh[n * XSB + c4 * 4] = *(const uint2*)&g_wh[p][n * DIN + kb + c4 * 4];
            *(uint2*)&wl[n * XSB + c4 * 4] = *(const uint2*)&g_wl[p][n * DIN + kb + c4 * 4];
        }
        __syncthreads();

        #pragma unroll
        for (int kc = 0; kc < 2; kc++) {
            const int ra = w * 16 + g, k0 = kc * 16 + 2 * t;
            uint32_t ah[4], al[4];
            ah[0] = *(const uint32_t*)&xh[ra * XSB + k0];
            ah[1] = *(const uint32_t*)&xh[(ra + 8) * XSB + k0];
            ah[2] = *(const uint32_t*)&xh[ra * XSB + k0 + 8];
            ah[3] = *(const uint32_t*)&xh[(ra + 8) * XSB + k0 + 8];
            al[0] = *(const uint32_t*)&xl[ra * XSB + k0];
            al[1] = *(const uint32_t*)&xl[(ra + 8) * XSB + k0];
            al[2] = *(const uint32_t*)&xl[ra * XSB + k0 + 8];
            al[3] = *(const uint32_t*)&xl[(ra + 8) * XSB + k0 + 8];
            #pragma unroll
            for (int nf = 0; nf < 8; nf++) {
                const int nr = nf * 8 + g;
                uint32_t b0 = *(const uint32_t*)&wh[nr * XSB + k0];
                uint32_t b1 = *(const uint32_t*)&wh[nr * XSB + k0 + 8];
                uint32_t d0 = *(const uint32_t*)&wl[nr * XSB + k0];
                uint32_t d1 = *(const uint32_t*)&wl[nr * XSB + k0 + 8];
                mma_bf16(c[nf], ah, b0, b1);
                mma_bf16(c[nf], al, b0, b1);
                mma_bf16(c[nf], ah, d0, d1);
            }
        }
    }

    // epilogue
    const int rowA = r0 + w * 16 + g, rowB = rowA + 8;
    if (p == 2) {
        #pragma unroll
        for (int nf = 0; nf < 8; nf++) {
            int c0 = nf * 8 + 2 * t;
            float vals[4] = {c[nf][0], c[nf][1], c[nf][2], c[nf][3]};
            int cols[4] = {c0, c0 + 1, c0, c0 + 1};
            int rows[4] = {rowA, rowA, rowB, rowB};
            #pragma unroll
            for (int q = 0; q < 4; q++) {
                __nv_bfloat16 h = __float2bfloat16(vals[q]);
                g_vh[cols[q] * SEQ + rows[q]] = h;
                g_vl[cols[q] * SEQ + rows[q]] =
                    __float2bfloat16(vals[q] - __bfloat162float(h));
            }
        }
    } else {
        __nv_bfloat16* dh = (p == 0) ? g_qh : g_kh;
        __nv_bfloat16* dl = (p == 0) ? g_ql : g_kl;
        const float sc = (p == 0) ? QK_SCALE : 1.0f;
        #pragma unroll
        for (int nf = 0; nf < 8; nf++) {
            uint32_t hA, lA, hB, lB;
            bsplit2(c[nf][0] * sc, c[nf][1] * sc, hA, lA);
            bsplit2(c[nf][2] * sc, c[nf][3] * sc, hB, lB);
            int off = nf * 8 + 2 * t;
            *(uint32_t*)&dh[rowA * D + off] = hA;
            *(uint32_t*)&dl[rowA * D + off] = lA;
            *(uint32_t*)&dh[rowB * D + off] = hB;
            *(uint32_t*)&dl[rowB * D + off] = lB;
        }
    }
}

// ---------------------------------------------------------------------------
// Kernel 2: flash attention, persistent balanced grid + double-buffered loads.
// Work unit u: row block (u>>4)*64, KV slice (u&15)*512 keys (8 tiles of 64).
// ---------------------------------------------------------------------------
#define ATT_SMEM (2 * BUFB)   // 73728 B

__global__ __launch_bounds__(128, 2) void attn_kernel() {
    extern __shared__ __nv_bfloat16 smb[];
    const uint32_t sbase = smem_u32(smb);

    const int tid = threadIdx.x, w = tid >> 5, lane = tid & 31;
    const int g = lane >> 2, t = lane & 3;

    auto issue_tile = [&](int kt, int buf) {
        #pragma unroll
        for (int i = tid; i < 2048; i += 128) {
            int arr = i >> 9, rem = i & 511, r = rem >> 3, c8 = rem & 7;
            const __nv_bfloat16* src;
            if      (arr == 0) src = &g_kh[(kt + r) * D + c8 * 8];
            else if (arr == 1) src = &g_kl[(kt + r) * D + c8 * 8];
            else if (arr == 2) src = &g_vh[r * SEQ + kt + c8 * 8];
            else               src = &g_vl[r * SEQ + kt + c8 * 8];
            uint32_t dst = sbase + (uint32_t)buf * BUFB
                         + (uint32_t)(arr * 64 * KST + r * KST + c8 * 8) * 2u;
            cp16(dst, src);
        }
        CP_COMMIT();
    };

    bool first = true;
    for (int u = blockIdx.x; u < TOTAL_UNITS; u += GRID_ATTN) {
        const int rb = u >> 4, sl = u & 15;
        const int k0 = sl * (TILES_PER_UNIT * BN);
        const int rowA = rb * 64 + w * 16 + g, rowB = rowA + 8;

        if (first) { issue_tile(k0, 0); first = false; }

        // Q fragments for this row block
        uint32_t qh[4][4], ql[4][4];
        #pragma unroll
        for (int kc = 0; kc < 4; kc++) {
            int kk0 = kc * 16 + 2 * t;
            qh[kc][0] = *(const uint32_t*)&g_qh[rowA * D + kk0];
            qh[kc][1] = *(const uint32_t*)&g_qh[rowB * D + kk0];
            qh[kc][2] = *(const uint32_t*)&g_qh[rowA * D + kk0 + 8];
            qh[kc][3] = *(const uint32_t*)&g_qh[rowB * D + kk0 + 8];
            ql[kc][0] = *(const uint32_t*)&g_ql[rowA * D + kk0];
            ql[kc][1] = *(const uint32_t*)&g_ql[rowB * D + kk0];
            ql[kc][2] = *(const uint32_t*)&g_ql[rowA * D + kk0 + 8];
            ql[kc][3] = *(const uint32_t*)&g_ql[rowB * D + kk0 + 8];
        }

        float o[8][4];
        #pragma unroll
        for (int nf = 0; nf < 8; nf++)
            #pragma unroll
            for (int i = 0; i < 4; i++) o[nf][i] = 0.0f;
        float m_a = -INFINITY, m_b = -INFINITY, l_a = 0.0f, l_b = 0.0f;

        for (int tt = 0; tt < TILES_PER_UNIT; tt++) {
            CP_WAIT0();
            __syncthreads();
            // prefetch next tile (or next unit's first tile) into the other buf
            if (tt + 1 < TILES_PER_UNIT) {
                issue_tile(k0 + (tt + 1) * BN, (tt + 1) & 1);
            } else {
                int u2 = u + GRID_ATTN;
                if (u2 < TOTAL_UNITS) issue_tile((u2 & 15) * (TILES_PER_UNIT * BN), 0);
            }

            const __nv_bfloat16* kh = smb + (tt & 1) * (BUFB / 2);
            const __nv_bfloat16* kl = kh + 64 * KST;
            const __nv_bfloat16* vh = kl + 64 * KST;
            const __nv_bfloat16* vl = vh + 64 * KST;

            // ---- S = Q K^T : bf16 3-pass ----
            float s_[8][4];
            #pragma unroll
            for (int j = 0; j < 8; j++)
                #pragma unroll
                for (int i = 0; i < 4; i++) s_[j][i] = 0.0f;
            #pragma unroll
            for (int j = 0; j < 8; j++) {
                const __nv_bfloat16* bh = &kh[(j * 8 + g) * KST];
                const __nv_bfloat16* bl = &kl[(j * 8 + g) * KST];
                #pragma unroll
                for (int kc = 0; kc < 4; kc++) {
                    uint32_t b0 = *(const uint32_t*)&bh[kc * 16 + 2 * t];
                    uint32_t b1 = *(const uint32_t*)&bh[kc * 16 + 2 * t + 8];
                    uint32_t d0 = *(const uint32_t*)&bl[kc * 16 + 2 * t];
                    uint32_t d1 = *(const uint32_t*)&bl[kc * 16 + 2 * t + 8];
                    mma_bf16(s_[j], qh[kc], b0, b1);
                    mma_bf16(s_[j], ql[kc], b0, b1);
                    mma_bf16(s_[j], qh[kc], d0, d1);
                }
            }

            // ---- online softmax (base-2) ----
            float mxa = -INFINITY, mxb = -INFINITY;
            #pragma unroll
            for (int j = 0; j < 8; j++) {
                mxa = fmaxf(mxa, fmaxf(s_[j][0], s_[j][1]));
                mxb = fmaxf(mxb, fmaxf(s_[j][2], s_[j][3]));
            }
            mxa = fmaxf(mxa, __shfl_xor_sync(0xffffffffu, mxa, 1));
            mxa = fmaxf(mxa, __shfl_xor_sync(0xffffffffu, mxa, 2));
            mxb = fmaxf(mxb, __shfl_xor_sync(0xffffffffu, mxb, 1));
            mxb = fmaxf(mxb, __shfl_xor_sync(0xffffffffu, mxb, 2));
            float mna = fmaxf(m_a, mxa), mnb = fmaxf(m_b, mxb);
            float ca = ex2(m_a - mna), cb = ex2(m_b - mnb);
            m_a = mna; m_b = mnb;
            float ra = 0.0f, rb2 = 0.0f;
            #pragma unroll
            for (int j = 0; j < 8; j++) {
                s_[j][0] = ex2(s_[j][0] - m_a);
                s_[j][1] = ex2(s_[j][1] - m_a);
                s_[j][2] = ex2(s_[j][2] - m_b);
                s_[j][3] = ex2(s_[j][3] - m_b);
                ra  += s_[j][0] + s_[j][1];
                rb2 += s_[j][2] + s_[j][3];
            }
            l_a = l_a * ca + ra;
            l_b = l_b * cb + rb2;
            #pragma unroll
            for (int nf = 0; nf < 8; nf++) {
                o[nf][0] *= ca; o[nf][1] *= ca;
                o[nf][2] *= cb; o[nf][3] *= cb;
            }

            // ---- pack P (hi only) ----
            uint32_t ah[4][4];
            #pragma unroll
            for (int kk = 0; kk < 4; kk++) {
                ah[kk][0] = pack_bf16(s_[2 * kk][0], s_[2 * kk][1]);
                ah[kk][1] = pack_bf16(s_[2 * kk][2], s_[2 * kk][3]);
                ah[kk][2] = pack_bf16(s_[2 * kk + 1][0], s_[2 * kk + 1][1]);
                ah[kk][3] = pack_bf16(s_[2 * kk + 1][2], s_[2 * kk + 1][3]);
            }

            // ---- O += P V : 2 passes ----
            #pragma unroll
            for (int nf = 0; nf < 8; nf++) {
                const __nv_bfloat16* bh = &vh[(nf * 8 + g) * KST];
                const __nv_bfloat16* bl = &vl[(nf * 8 + g) * KST];
                #pragma unroll
                for (int kk = 0; kk < 4; kk++) {
                    uint32_t b0 = *(const uint32_t*)&bh[kk * 16 + 2 * t];
                    uint32_t b1 = *(const uint32_t*)&bh[kk * 16 + 2 * t + 8];
                    uint32_t d0 = *(const uint32_t*)&bl[kk * 16 + 2 * t];
                    uint32_t d1 = *(const uint32_t*)&bl[kk * 16 + 2 * t + 8];
                    mma_bf16(o[nf], ah[kk], b0, b1);
                    mma_bf16(o[nf], ah[kk], d0, d1);
                }
            }
        }

        // ---- unit epilogue: reduce l across quad, store partials ----
        float la = l_a + __shfl_xor_sync(0xffffffffu, l_a, 1);
        la += __shfl_xor_sync(0xffffffffu, la, 2);
        float lb = l_b + __shfl_xor_sync(0xffffffffu, l_b, 1);
        lb += __shfl_xor_sync(0xffffffffu, lb, 2);

        #pragma unroll
        for (int nf = 0; nf < 8; nf++) {
            g_po[sl][rowA * D + nf * 8 + 2 * t]     = o[nf][0];
            g_po[sl][rowA * D + nf * 8 + 2 * t + 1] = o[nf][1];
            g_po[sl][rowB * D + nf * 8 + 2 * t]     = o[nf][2];
            g_po[sl][rowB * D + nf * 8 + 2 * t + 1] = o[nf][3];
        }
        if (t == 0) {
            g_pm[sl][rowA] = m_a; g_pl[sl][rowA] = la;
            g_pm[sl][rowB] = m_b; g_pl[sl][rowB] = lb;
        }
    }
}

// ---------------------------------------------------------------------------
// Kernel 3: combine the 16 KV slices.  Block = 256 threads = 4 rows.
// ---------------------------------------------------------------------------
__global__ void combine_kernel(float* __restrict__ out) {
    __shared__ float ws[4][NSPLIT];
    const int tid = threadIdx.x;
    const int r0 = blockIdx.x * 4;

    if (tid < 4) {
        int r = r0 + tid;
        float M = -INFINITY;
        #pragma unroll
        for (int i = 0; i < NSPLIT; i++) M = fmaxf(M, g_pm[i][r]);
        float wv[NSPLIT];
        float den = 0.0f;
        #pragma unroll
        for (int i = 0; i < NSPLIT; i++) {
            wv[i] = ex2(g_pm[i][r] - M);
            den += g_pl[i][r] * wv[i];
        }
        float inv = __frcp_rn(den);
        #pragma unroll
        for (int i = 0; i < NSPLIT; i++) ws[tid][i] = wv[i] * inv;
    }
    __syncthreads();

    int idx = blockIdx.x * 256 + tid;
    int rloc = (idx >> 6) & 3;
    float acc = 0.0f;
    #pragma unroll
    for (int i = 0; i < NSPLIT; i++)
        acc += g_po[i][idx] * ws[rloc][i];
    out[idx] = acc;
}

// ---------------------------------------------------------------------------
extern "C" void kernel_launch(void* const* d_in, const int* in_sizes, int n_in,
                              void* d_out, int out_size) {
    const float* x  = (const float*)d_in[0];
    const float* Wq = (const float*)d_in[1];
    const float* Wk = (const float*)d_in[2];
    const float* Wv = (const float*)d_in[3];
    float* out = (float*)d_out;

    cudaFuncSetAttribute(qkv_kernel,
                         cudaFuncAttributeMaxDynamicSharedMemorySize, QKV_SMEM);
    cudaFuncSetAttribute(attn_kernel,
                         cudaFuncAttributeMaxDynamicSharedMemorySize, ATT_SMEM);

    prep_kernel<<<(3 * D * DIN) / 256, 256>>>(Wq, Wk, Wv);
    qkv_kernel<<<dim3(SEQ / 128, 3), 256, QKV_SMEM>>>(x);
    attn_kernel<<<GRID_ATTN, 128, ATT_SMEM>>>();
    combine_kernel<<<SEQ / 4, 256>>>(out);
}

// round 7
// speedup vs baseline: 4.4198x; 1.0670x over previous
#include <cuda_runtime.h>
#include <cuda_bf16.h>
#include <cstdint>
#include <math.h>

#define SEQ 8192
#define DIN 512
#define D   64
#define BN  64
#define NSPLIT 16
#define TILES_PER_UNIT 8            // 8 * 64 = 512 keys per unit
#define TOTAL_UNITS (128 * NSPLIT)  // 2048
#define GRID_ATTN 304               // 2 CTAs x 152 SMs (GB300)
#define QK_SCALE 0.18033688011112042f   // 0.125 * log2(e)
#define XSB 40      // qkv smem row stride (bf16)
#define KST 72      // attn smem row stride (bf16)
#define BUFB (4 * 64 * KST * 2)     // one attn buffer: 36864 B

// ---------------- device scratch (no cudaMalloc allowed) ----------------
__device__ __nv_bfloat16 g_wh[3][D * DIN], g_wl[3][D * DIN];   // W^T bf16 hi/lo
__device__ __nv_bfloat16 g_qh[SEQ * D], g_ql[SEQ * D];         // Q bf16 hi/lo (scaled)
__device__ __nv_bfloat16 g_kh[SEQ * D], g_kl[SEQ * D];         // K bf16 hi/lo
__device__ __nv_bfloat16 g_vh[D * SEQ], g_vl[D * SEQ];         // V^T bf16 hi/lo
__device__ float g_po[NSPLIT][SEQ * D];
__device__ float g_pm[NSPLIT][SEQ];
__device__ float g_pl[NSPLIT][SEQ];

// ---------------- helpers ----------------
__device__ __forceinline__ float ex2(float x) {
    float r; asm("ex2.approx.f32 %0, %1;" : "=f"(r) : "f"(x)); return r;
}
__device__ __forceinline__ void mma_bf16(float* c, const uint32_t* a,
                                         uint32_t b0, uint32_t b1) {
    asm volatile(
        "mma.sync.aligned.m16n8k16.row.col.f32.bf16.bf16.f32 "
        "{%0,%1,%2,%3},{%4,%5,%6,%7},{%8,%9},{%0,%1,%2,%3};"
        : "+f"(c[0]), "+f"(c[1]), "+f"(c[2]), "+f"(c[3])
        : "r"(a[0]), "r"(a[1]), "r"(a[2]), "r"(a[3]), "r"(b0), "r"(b1));
}
__device__ __forceinline__ void ldm_x4(uint32_t& r0, uint32_t& r1,
                                       uint32_t& r2, uint32_t& r3, uint32_t addr) {
    asm volatile("ldmatrix.sync.aligned.m8n8.x4.shared.b16 {%0,%1,%2,%3}, [%4];"
                 : "=r"(r0), "=r"(r1), "=r"(r2), "=r"(r3) : "r"(addr));
}
__device__ __forceinline__ uint32_t pack_bf16(float lo, float hi) {
    uint32_t r;
    asm("cvt.rn.bf16x2.f32 %0, %1, %2;" : "=r"(r) : "f"(hi), "f"(lo));
    return r;
}
__device__ __forceinline__ void bsplit2(float v0, float v1, uint32_t& h, uint32_t& l) {
    __nv_bfloat16 h0 = __float2bfloat16(v0), h1 = __float2bfloat16(v1);
    float l0 = v0 - __bfloat162float(h0), l1 = v1 - __bfloat162float(h1);
    __nv_bfloat162 hh(h0, h1);
    __nv_bfloat162 ll(__float2bfloat16(l0), __float2bfloat16(l1));
    h = *(uint32_t*)&hh;
    l = *(uint32_t*)&ll;
}
__device__ __forceinline__ uint32_t smem_u32(const void* p) {
    uint32_t a;
    asm("{ .reg .u64 t; cvta.to.shared.u64 t, %1; cvt.u32.u64 %0, t; }" : "=r"(a) : "l"(p));
    return a;
}
__device__ __forceinline__ void cp16(uint32_t dst, const void* src) {
    asm volatile("cp.async.cg.shared.global [%0], [%1], 16;" :: "r"(dst), "l"(src) : "memory");
}
#define CP_COMMIT() asm volatile("cp.async.commit_group;" ::: "memory")
#define CP_WAIT0()  asm volatile("cp.async.wait_group 0;" ::: "memory")
#define CP_WAIT1()  asm volatile("cp.async.wait_group 1;" ::: "memory")

// ---------------------------------------------------------------------------
// Kernel 0: split W^T into bf16 hi/lo.
// ---------------------------------------------------------------------------
__global__ void prep_kernel(const float* __restrict__ Wq,
                            const float* __restrict__ Wk,
                            const float* __restrict__ Wv) {
    int i = blockIdx.x * 256 + threadIdx.x;          // < 3*D*DIN
    int p = i / (D * DIN), r = i % (D * DIN);
    int n = r / DIN, k = r % DIN;
    const float* W = (p == 0) ? Wq : (p == 1) ? Wk : Wv;
    float w = W[k * D + n];
    __nv_bfloat16 h = __float2bfloat16(w);
    g_wh[p][n * DIN + k] = h;
    g_wl[p][n * DIN + k] = __float2bfloat16(w - __bfloat162float(h));
}

// ---------------------------------------------------------------------------
// Kernel 1: QKV projection via bf16 2-split 3-pass mma.  grid (SEQ/128, 3).
// ---------------------------------------------------------------------------
#define QKV_SMEM ((128 * XSB * 2 + 64 * XSB * 2) * 2)   // 30720 B

__global__ __launch_bounds__(256, 2) void qkv_kernel(const float* __restrict__ x) {
    extern __shared__ __nv_bfloat16 qsm[];
    __nv_bfloat16* xh = qsm;                 // [128][XSB]
    __nv_bfloat16* xl = xh + 128 * XSB;
    __nv_bfloat16* wh = xl + 128 * XSB;      // [64][XSB]
    __nv_bfloat16* wl = wh + 64 * XSB;

    const int tid = threadIdx.x, w = tid >> 5, lane = tid & 31;
    const int g = lane >> 2, t = lane & 3;
    const int r0 = blockIdx.x * 128;
    const int p = blockIdx.y;

    float c[8][4];
    #pragma unroll
    for (int nf = 0; nf < 8; nf++)
        #pragma unroll
        for (int i = 0; i < 4; i++) c[nf][i] = 0.0f;

    for (int kb = 0; kb < DIN; kb += 32) {
        __syncthreads();
        #pragma unroll
        for (int i = tid; i < 1024; i += 256) {
            int r = i >> 3, c4 = i & 7;
            float4 v = *(const float4*)&x[(r0 + r) * DIN + kb + c4 * 4];
            uint32_t h0, l0, h1, l1;
            bsplit2(v.x, v.y, h0, l0);
            bsplit2(v.z, v.w, h1, l1);
            *(uint2*)&xh[r * XSB + c4 * 4] = make_uint2(h0, h1);
            *(uint2*)&xl[r * XSB + c4 * 4] = make_uint2(l0, l1);
        }
        #pragma unroll
        for (int i = tid; i < 512; i += 256) {
            int n = i >> 3, c4 = i & 7;
            *(uint2*)&wh[n * XSB + c4 * 4] = *(const uint2*)&g_wh[p][n * DIN + kb + c4 * 4];
            *(uint2*)&wl[n * XSB + c4 * 4] = *(const uint2*)&g_wl[p][n * DIN + kb + c4 * 4];
        }
        __syncthreads();

        #pragma unroll
        for (int kc = 0; kc < 2; kc++) {
            const int ra = w * 16 + g, k0 = kc * 16 + 2 * t;
            uint32_t ah[4], al[4];
            ah[0] = *(const uint32_t*)&xh[ra * XSB + k0];
            ah[1] = *(const uint32_t*)&xh[(ra + 8) * XSB + k0];
            ah[2] = *(const uint32_t*)&xh[ra * XSB + k0 + 8];
            ah[3] = *(const uint32_t*)&xh[(ra + 8) * XSB + k0 + 8];
            al[0] = *(const uint32_t*)&xl[ra * XSB + k0];
            al[1] = *(const uint32_t*)&xl[(ra + 8) * XSB + k0];
            al[2] = *(const uint32_t*)&xl[ra * XSB + k0 + 8];
            al[3] = *(const uint32_t*)&xl[(ra + 8) * XSB + k0 + 8];
            #pragma unroll
            for (int nf = 0; nf < 8; nf++) {
                const int nr = nf * 8 + g;
                uint32_t b0 = *(const uint32_t*)&wh[nr * XSB + k0];
                uint32_t b1 = *(const uint32_t*)&wh[nr * XSB + k0 + 8];
                uint32_t d0 = *(const uint32_t*)&wl[nr * XSB + k0];
                uint32_t d1 = *(const uint32_t*)&wl[nr * XSB + k0 + 8];
                mma_bf16(c[nf], ah, b0, b1);
                mma_bf16(c[nf], al, b0, b1);
                mma_bf16(c[nf], ah, d0, d1);
            }
        }
    }

    const int rowA = r0 + w * 16 + g, rowB = rowA + 8;
    if (p == 2) {
        #pragma unroll
        for (int nf = 0; nf < 8; nf++) {
            int c0 = nf * 8 + 2 * t;
            float vals[4] = {c[nf][0], c[nf][1], c[nf][2], c[nf][3]};
            int cols[4] = {c0, c0 + 1, c0, c0 + 1};
            int rows[4] = {rowA, rowA, rowB, rowB};
            #pragma unroll
            for (int q = 0; q < 4; q++) {
                __nv_bfloat16 h = __float2bfloat16(vals[q]);
                g_vh[cols[q] * SEQ + rows[q]] = h;
                g_vl[cols[q] * SEQ + rows[q]] =
                    __float2bfloat16(vals[q] - __bfloat162float(h));
            }
        }
    } else {
        __nv_bfloat16* dh = (p == 0) ? g_qh : g_kh;
        __nv_bfloat16* dl = (p == 0) ? g_ql : g_kl;
        const float sc = (p == 0) ? QK_SCALE : 1.0f;
        #pragma unroll
        for (int nf = 0; nf < 8; nf++) {
            uint32_t hA, lA, hB, lB;
            bsplit2(c[nf][0] * sc, c[nf][1] * sc, hA, lA);
            bsplit2(c[nf][2] * sc, c[nf][3] * sc, hB, lB);
            int off = nf * 8 + 2 * t;
            *(uint32_t*)&dh[rowA * D + off] = hA;
            *(uint32_t*)&dl[rowA * D + off] = lA;
            *(uint32_t*)&dh[rowB * D + off] = hB;
            *(uint32_t*)&dl[rowB * D + off] = lB;
        }
    }
}

// ---------------------------------------------------------------------------
// Kernel 2: flash attention, persistent grid, true double-buffered cp.async,
// ldmatrix B-fragment loads.
// ---------------------------------------------------------------------------
#define ATT_SMEM (2 * BUFB)   // 73728 B

__global__ __launch_bounds__(128, 2) void attn_kernel() {
    extern __shared__ __nv_bfloat16 smb[];
    const uint32_t sbase = smem_u32(smb);

    const int tid = threadIdx.x, w = tid >> 5, lane = tid & 31;
    const int g = lane >> 2, t = lane & 3;

    // per-lane ldmatrix address component: row (lane&7), halves (lane>>3)*8 elems
    const uint32_t lmo = (uint32_t)((lane & 7) * KST + (lane >> 3) * 8) * 2u;

    auto issue_tile = [&](int kt, int buf) {
        #pragma unroll
        for (int i = tid; i < 2048; i += 128) {
            int arr = i >> 9, rem = i & 511, r = rem >> 3, c8 = rem & 7;
            const __nv_bfloat16* src;
            if      (arr == 0) src = &g_kh[(kt + r) * D + c8 * 8];
            else if (arr == 1) src = &g_kl[(kt + r) * D + c8 * 8];
            else if (arr == 2) src = &g_vh[r * SEQ + kt + c8 * 8];
            else               src = &g_vl[r * SEQ + kt + c8 * 8];
            uint32_t dst = sbase + (uint32_t)buf * BUFB
                         + (uint32_t)(arr * 64 * KST + r * KST + c8 * 8) * 2u;
            cp16(dst, src);
        }
        CP_COMMIT();
    };

    bool first = true;
    for (int u = blockIdx.x; u < TOTAL_UNITS; u += GRID_ATTN) {
        const int rb = u >> 4, sl = u & 15;
        const int k0 = sl * (TILES_PER_UNIT * BN);
        const int rowA = rb * 64 + w * 16 + g, rowB = rowA + 8;

        if (first) { issue_tile(k0, 0); first = false; }

        // Q fragments
        uint32_t qh[4][4], ql[4][4];
        #pragma unroll
        for (int kc = 0; kc < 4; kc++) {
            int kk0 = kc * 16 + 2 * t;
            qh[kc][0] = *(const uint32_t*)&g_qh[rowA * D + kk0];
            qh[kc][1] = *(const uint32_t*)&g_qh[rowB * D + kk0];
            qh[kc][2] = *(const uint32_t*)&g_qh[rowA * D + kk0 + 8];
            qh[kc][3] = *(const uint32_t*)&g_qh[rowB * D + kk0 + 8];
            ql[kc][0] = *(const uint32_t*)&g_ql[rowA * D + kk0];
            ql[kc][1] = *(const uint32_t*)&g_ql[rowB * D + kk0];
            ql[kc][2] = *(const uint32_t*)&g_ql[rowA * D + kk0 + 8];
            ql[kc][3] = *(const uint32_t*)&g_ql[rowB * D + kk0 + 8];
        }

        float o[8][4];
        #pragma unroll
        for (int nf = 0; nf < 8; nf++)
            #pragma unroll
            for (int i = 0; i < 4; i++) o[nf][i] = 0.0f;
        float m_a = -INFINITY, m_b = -INFINITY, l_a = 0.0f, l_b = 0.0f;

        for (int tt = 0; tt < TILES_PER_UNIT; tt++) {
            // prefetch next tile into the other buffer, then wait for current
            bool pref = true;
            if (tt + 1 < TILES_PER_UNIT) {
                issue_tile(k0 + (tt + 1) * BN, (tt + 1) & 1);
            } else {
                int u2 = u + GRID_ATTN;
                if (u2 < TOTAL_UNITS) issue_tile((u2 & 15) * (TILES_PER_UNIT * BN), 0);
                else pref = false;
            }
            if (pref) { CP_WAIT1(); } else { CP_WAIT0(); }
            __syncthreads();

            const uint32_t tb = sbase + (uint32_t)(tt & 1) * BUFB;
            const uint32_t akh = tb + lmo;
            const uint32_t akl = akh + (uint32_t)(64 * KST) * 2u;
            const uint32_t avh = akl + (uint32_t)(64 * KST) * 2u;
            const uint32_t avl = avh + (uint32_t)(64 * KST) * 2u;

            // ---- S = Q K^T : bf16 3-pass, ldmatrix B-frags ----
            float s_[8][4];
            #pragma unroll
            for (int j = 0; j < 8; j++)
                #pragma unroll
                for (int i = 0; i < 4; i++) s_[j][i] = 0.0f;
            #pragma unroll
            for (int j = 0; j < 8; j++) {
                const uint32_t rj = (uint32_t)(j * 8 * KST) * 2u;
                uint32_t h[8], l[8];
                ldm_x4(h[0], h[1], h[2], h[3], akh + rj);
                ldm_x4(h[4], h[5], h[6], h[7], akh + rj + 64);
                ldm_x4(l[0], l[1], l[2], l[3], akl + rj);
                ldm_x4(l[4], l[5], l[6], l[7], akl + rj + 64);
                #pragma unroll
                for (int kc = 0; kc < 4; kc++) {
                    mma_bf16(s_[j], qh[kc], h[2 * kc], h[2 * kc + 1]);
                    mma_bf16(s_[j], ql[kc], h[2 * kc], h[2 * kc + 1]);
                    mma_bf16(s_[j], qh[kc], l[2 * kc], l[2 * kc + 1]);
                }
            }

            // ---- online softmax (base-2) ----
            float mxa = -INFINITY, mxb = -INFINITY;
            #pragma unroll
            for (int j = 0; j < 8; j++) {
                mxa = fmaxf(mxa, fmaxf(s_[j][0], s_[j][1]));
                mxb = fmaxf(mxb, fmaxf(s_[j][2], s_[j][3]));
            }
            mxa = fmaxf(mxa, __shfl_xor_sync(0xffffffffu, mxa, 1));
            mxa = fmaxf(mxa, __shfl_xor_sync(0xffffffffu, mxa, 2));
            mxb = fmaxf(mxb, __shfl_xor_sync(0xffffffffu, mxb, 1));
            mxb = fmaxf(mxb, __shfl_xor_sync(0xffffffffu, mxb, 2));
            float mna = fmaxf(m_a, mxa), mnb = fmaxf(m_b, mxb);
            float ca = ex2(m_a - mna), cb = ex2(m_b - mnb);
            m_a = mna; m_b = mnb;
            float ra = 0.0f, rb2 = 0.0f;
            #pragma unroll
            for (int j = 0; j < 8; j++) {
                s_[j][0] = ex2(s_[j][0] - m_a);
                s_[j][1] = ex2(s_[j][1] - m_a);
                s_[j][2] = ex2(s_[j][2] - m_b);
                s_[j][3] = ex2(s_[j][3] - m_b);
                ra  += s_[j][0] + s_[j][1];
                rb2 += s_[j][2] + s_[j][3];
            }
            l_a = l_a * ca + ra;
            l_b = l_b * cb + rb2;
            #pragma unroll
            for (int nf = 0; nf < 8; nf++) {
                o[nf][0] *= ca; o[nf][1] *= ca;
                o[nf][2] *= cb; o[nf][3] *= cb;
            }

            // ---- pack P (hi only) ----
            uint32_t ah[4][4];
            #pragma unroll
            for (int kk = 0; kk < 4; kk++) {
                ah[kk][0] = pack_bf16(s_[2 * kk][0], s_[2 * kk][1]);
                ah[kk][1] = pack_bf16(s_[2 * kk][2], s_[2 * kk][3]);
                ah[kk][2] = pack_bf16(s_[2 * kk + 1][0], s_[2 * kk + 1][1]);
                ah[kk][3] = pack_bf16(s_[2 * kk + 1][2], s_[2 * kk + 1][3]);
            }

            // ---- O += P V : 2 passes, ldmatrix B-frags ----
            #pragma unroll
            for (int nf = 0; nf < 8; nf++) {
                const uint32_t rn = (uint32_t)(nf * 8 * KST) * 2u;
                uint32_t h[8], l[8];
                ldm_x4(h[0], h[1], h[2], h[3], avh + rn);
                ldm_x4(h[4], h[5], h[6], h[7], avh + rn + 64);
                ldm_x4(l[0], l[1], l[2], l[3], avl + rn);
                ldm_x4(l[4], l[5], l[6], l[7], avl + rn + 64);
                #pragma unroll
                for (int kk = 0; kk < 4; kk++) {
                    mma_bf16(o[nf], ah[kk], h[2 * kk], h[2 * kk + 1]);
                    mma_bf16(o[nf], ah[kk], l[2 * kk], l[2 * kk + 1]);
                }
            }
            __syncthreads();   // all warps done with this buffer
        }

        // ---- unit epilogue ----
        float la = l_a + __shfl_xor_sync(0xffffffffu, l_a, 1);
        la += __shfl_xor_sync(0xffffffffu, la, 2);
        float lb = l_b + __shfl_xor_sync(0xffffffffu, l_b, 1);
        lb += __shfl_xor_sync(0xffffffffu, lb, 2);

        #pragma unroll
        for (int nf = 0; nf < 8; nf++) {
            *(float2*)&g_po[sl][rowA * D + nf * 8 + 2 * t] = make_float2(o[nf][0], o[nf][1]);
            *(float2*)&g_po[sl][rowB * D + nf * 8 + 2 * t] = make_float2(o[nf][2], o[nf][3]);
        }
        if (t == 0) {
            g_pm[sl][rowA] = m_a; g_pl[sl][rowA] = la;
            g_pm[sl][rowB] = m_b; g_pl[sl][rowB] = lb;
        }
    }
}

// ---------------------------------------------------------------------------
// Kernel 3: combine the 16 KV slices.  Block = 256 threads = 4 rows.
// ---------------------------------------------------------------------------
__global__ void combine_kernel(float* __restrict__ out) {
    __shared__ float ws[4][NSPLIT];
    const int tid = threadIdx.x;
    const int r0 = blockIdx.x * 4;

    if (tid < 4) {
        int r = r0 + tid;
        float M = -INFINITY;
        #pragma unroll
        for (int i = 0; i < NSPLIT; i++) M = fmaxf(M, g_pm[i][r]);
        float wv[NSPLIT];
        float den = 0.0f;
        #pragma unroll
        for (int i = 0; i < NSPLIT; i++) {
            wv[i] = ex2(g_pm[i][r] - M);
            den += g_pl[i][r] * wv[i];
        }
        float inv = __frcp_rn(den);
        #pragma unroll
        for (int i = 0; i < NSPLIT; i++) ws[tid][i] = wv[i] * inv;
    }
    __syncthreads();

    int idx = blockIdx.x * 256 + tid;
    int rloc = (idx >> 6) & 3;
    float acc = 0.0f;
    #pragma unroll
    for (int i = 0; i < NSPLIT; i++)
        acc += g_po[i][idx] * ws[rloc][i];
    out[idx] = acc;
}

// ---------------------------------------------------------------------------
extern "C" void kernel_launch(void* const* d_in, const int* in_sizes, int n_in,
                              void* d_out, int out_size) {
    const float* x  = (const float*)d_in[0];
    const float* Wq = (const float*)d_in[1];
    const float* Wk = (const float*)d_in[2];
    const float* Wv = (const float*)d_in[3];
    float* out = (float*)d_out;

    cudaFuncSetAttribute(qkv_kernel,
                         cudaFuncAttributeMaxDynamicSharedMemorySize, QKV_SMEM);
    cudaFuncSetAttribute(attn_kernel,
                         cudaFuncAttributeMaxDynamicSharedMemorySize, ATT_SMEM);

    prep_kernel<<<(3 * D * DIN) / 256, 256>>>(Wq, Wk, Wv);
    qkv_kernel<<<dim3(SEQ / 128, 3), 256, QKV_SMEM>>>(x);
    attn_kernel<<<GRID_ATTN, 128, ATT_SMEM>>>();
    combine_kernel<<<SEQ / 4, 256>>>(out);
}